// round 4
// baseline (speedup 1.0000x reference)
#include <cuda_runtime.h>
#include <cuda_fp16.h>
#include <cstdint>

// NF4 fused dequant GEMM: out[M,N] = fp16(x[M,K] @ W^T) + fp16 bias, emitted as fp32.
// Harness dtypes (theory): x fp32, weight_packed int32 (one code byte per int32),
// absmax fp32, bias fp32, out fp32.  M=4096, K=4096, N=11008.
// Quant BLOCK_SIZE=64 aligns exactly with BK=64.

#define BM 128
#define BN 128
#define BK 64
#define LDT 72            // BK + 8 halfs pad (144B row stride, 16B multiple)
#define THREADS 256

__constant__ float c_nf4[16] = {
    -1.0f, -0.6961928009986877f, -0.5250730514526367f, -0.39491748809814453f,
    -0.28444138169288635f, -0.18477343022823334f, -0.09105003625154495f, 0.0f,
    0.07958029955625534f, 0.16093020141124725f, 0.24611230194568634f,
    0.33791524171829224f, 0.44070982933044434f, 0.5626170039176941f,
    0.8072066307067871f, 1.0f};

__global__ __launch_bounds__(THREADS, 1)
void nf4_gemm_kernel(const float* __restrict__ X,
                     const int*   __restrict__ WP,
                     const float* __restrict__ AM,
                     const float* __restrict__ BIAS,
                     float*       __restrict__ OUT)
{
    constexpr int K     = 4096;
    constexpr int NOUT  = 11008;
    constexpr int KP    = 2048;   // code-carrying int32s per W row
    constexpr int NBLK  = 64;     // absmax blocks per row
    constexpr int STEPS = K / BK;
    constexpr int NB    = 11008 / BN;  // 86
    constexpr int GRPM  = 8;           // m-tiles per swizzle group

    extern __shared__ __half smem[];
    __half* As  = smem;                         // [2][BM*LDT]
    __half* Bs  = smem + 2 * BM * LDT;          // [2][BM*LDT]
    float*  tab = (float*)(Bs + 2 * BM * LDT);  // 16 floats

    const int tid = threadIdx.x;
    if (tid < 16) tab[tid] = c_nf4[tid];

    // Block swizzle: groups of 8 M-tiles sweep all N -> X stays L2-resident per group.
    const int bid = blockIdx.x;
    const int g   = bid / (GRPM * NB);
    const int rml = bid % (GRPM * NB);
    const int bm  = g * GRPM + (rml % GRPM);
    const int bn  = rml / GRPM;
    const int mBase = bm * BM;
    const int nBase = bn * BN;

    const int lane = tid & 31;
    const int wid  = tid >> 5;
    const int wm   = wid >> 2;   // 0..1  (64-row warp tile)
    const int wn   = wid & 3;    // 0..3  (32-col warp tile)

    const int r0_ = tid >> 3;    // tile row (stride 32 per i)
    const int c0_ = tid & 7;     // 8-element vector column

    float acc[4][4][4];
    #pragma unroll
    for (int m = 0; m < 4; m++)
        #pragma unroll
        for (int n = 0; n < 4; n++)
            #pragma unroll
            for (int q = 0; q < 4; q++) acc[m][n][q] = 0.f;

    float4 areg[4][2];
    int4   breg[4];
    float  sreg[4];

    auto load_tiles = [&](int k0) {
        #pragma unroll
        for (int i = 0; i < 4; i++) {
            int r = r0_ + 32 * i;
            const float* xp = X + (size_t)(mBase + r) * K + k0 + c0_ * 8;
            areg[i][0] = *(const float4*)(xp);
            areg[i][1] = *(const float4*)(xp + 4);
            breg[i] = *(const int4*)(WP + (size_t)(nBase + r) * KP + (k0 >> 1) + c0_ * 4);
            sreg[i] = __ldg(AM + (size_t)(nBase + r) * NBLK + (k0 >> 6));
        }
    };

    auto store_tiles = [&](int buf) {
        __half* Ab = As + buf * BM * LDT;
        __half* Bb = Bs + buf * BM * LDT;
        #pragma unroll
        for (int i = 0; i < 4; i++) {
            int r = r0_ + 32 * i;
            // X fp32 -> fp16 (matches reference's x.astype-equivalent cast)
            __half2 a01 = __floats2half2_rn(areg[i][0].x, areg[i][0].y);
            __half2 a23 = __floats2half2_rn(areg[i][0].z, areg[i][0].w);
            __half2 a45 = __floats2half2_rn(areg[i][1].x, areg[i][1].y);
            __half2 a67 = __floats2half2_rn(areg[i][1].z, areg[i][1].w);
            uint4 av;
            av.x = *reinterpret_cast<uint32_t*>(&a01);
            av.y = *reinterpret_cast<uint32_t*>(&a23);
            av.z = *reinterpret_cast<uint32_t*>(&a45);
            av.w = *reinterpret_cast<uint32_t*>(&a67);
            *(uint4*)(Ab + r * LDT + c0_ * 8) = av;

            float s = sreg[i];
            int vv[4] = {breg[i].x, breg[i].y, breg[i].z, breg[i].w};
            uint32_t u[4];
            #pragma unroll
            for (int j = 0; j < 4; j++) {
                int v = vv[j];  // one code byte: high nibble = even elem, low = odd
                __half2 h = __floats2half2_rn(tab[(v >> 4) & 15] * s, tab[v & 15] * s);
                u[j] = *reinterpret_cast<uint32_t*>(&h);
            }
            uint4 o; o.x = u[0]; o.y = u[1]; o.z = u[2]; o.w = u[3];
            *(uint4*)(Bb + r * LDT + c0_ * 8) = o;
        }
    };

    // prologue
    load_tiles(0);
    __syncthreads();          // tab visible to all threads
    store_tiles(0);
    __syncthreads();

    for (int kt = 0; kt < STEPS; kt++) {
        const int cur = kt & 1;
        if (kt + 1 < STEPS) load_tiles((kt + 1) * BK);

        const __half* Ab = As + cur * BM * LDT;
        const __half* Bb = Bs + cur * BM * LDT;
        #pragma unroll
        for (int kk = 0; kk < BK / 16; kk++) {
            uint32_t af[4][4];
            #pragma unroll
            for (int m = 0; m < 4; m++) {
                const __half* p = Ab + (wm * 64 + m * 16 + (lane & 15)) * LDT
                                     + kk * 16 + (lane >> 4) * 8;
                uint32_t addr = (uint32_t)__cvta_generic_to_shared(p);
                asm volatile(
                    "ldmatrix.sync.aligned.m8n8.x4.shared.b16 {%0,%1,%2,%3}, [%4];\n"
                    : "=r"(af[m][0]), "=r"(af[m][1]), "=r"(af[m][2]), "=r"(af[m][3])
                    : "r"(addr));
            }
            uint32_t bf[4][2];
            #pragma unroll
            for (int np = 0; np < 2; np++) {
                int grp = lane >> 3;
                const __half* p = Bb + (wn * 32 + np * 16 + (grp >> 1) * 8 + (lane & 7)) * LDT
                                     + kk * 16 + (grp & 1) * 8;
                uint32_t addr = (uint32_t)__cvta_generic_to_shared(p);
                uint32_t q0, q1, q2, q3;
                asm volatile(
                    "ldmatrix.sync.aligned.m8n8.x4.shared.b16 {%0,%1,%2,%3}, [%4];\n"
                    : "=r"(q0), "=r"(q1), "=r"(q2), "=r"(q3)
                    : "r"(addr));
                bf[np * 2][0] = q0; bf[np * 2][1] = q1;
                bf[np * 2 + 1][0] = q2; bf[np * 2 + 1][1] = q3;
            }
            #pragma unroll
            for (int m = 0; m < 4; m++)
                #pragma unroll
                for (int n = 0; n < 4; n++)
                    asm volatile(
                        "mma.sync.aligned.m16n8k16.row.col.f32.f16.f16.f32 "
                        "{%0,%1,%2,%3}, {%4,%5,%6,%7}, {%8,%9}, {%0,%1,%2,%3};\n"
                        : "+f"(acc[m][n][0]), "+f"(acc[m][n][1]),
                          "+f"(acc[m][n][2]), "+f"(acc[m][n][3])
                        : "r"(af[m][0]), "r"(af[m][1]), "r"(af[m][2]), "r"(af[m][3]),
                          "r"(bf[n][0]), "r"(bf[n][1]));
        }

        if (kt + 1 < STEPS) {
            store_tiles(cur ^ 1);
            __syncthreads();
        }
    }

    // epilogue: mimic reference rounding: fp16(dot) + fp16(bias) in fp16, emit fp32.
    #pragma unroll
    for (int n = 0; n < 4; n++) {
        int colBase = nBase + wn * 32 + n * 8 + 2 * (lane & 3);
        float b0 = __half2float(__float2half_rn(BIAS[colBase]));
        float b1 = __half2float(__float2half_rn(BIAS[colBase + 1]));
        #pragma unroll
        for (int m = 0; m < 4; m++) {
            int row0 = mBase + wm * 64 + m * 16 + (lane >> 2);
            float o00 = __half2float(__float2half_rn(
                          __half2float(__float2half_rn(acc[m][n][0])) + b0));
            float o01 = __half2float(__float2half_rn(
                          __half2float(__float2half_rn(acc[m][n][1])) + b1));
            float o10 = __half2float(__float2half_rn(
                          __half2float(__float2half_rn(acc[m][n][2])) + b0));
            float o11 = __half2float(__float2half_rn(
                          __half2float(__float2half_rn(acc[m][n][3])) + b1));
            float2 v0 = make_float2(o00, o01);
            float2 v1 = make_float2(o10, o11);
            *(float2*)(OUT + (size_t)row0 * NOUT + colBase) = v0;
            *(float2*)(OUT + (size_t)(row0 + 8) * NOUT + colBase) = v1;
        }
    }
}

extern "C" void kernel_launch(void* const* d_in, const int* in_sizes, int n_in,
                              void* d_out, int out_size)
{
    // Bind inputs by UNIQUE element counts (robust to metadata ordering):
    //   x:     16777216 (fp32 per dtype theory)
    //   wp:    22544384 (int32)
    //   amax:  704512   (fp32)
    //   bias:  11008    (fp32)
    const float* x    = nullptr;
    const int*   wp   = nullptr;
    const float* amax = nullptr;
    const float* bias = nullptr;
    for (int i = 0; i < n_in; i++) {
        switch (in_sizes[i]) {
            case 16777216: x    = (const float*)d_in[i]; break;
            case 22544384: wp   = (const int*)d_in[i];   break;
            case 704512:   amax = (const float*)d_in[i]; break;
            case 11008:    bias = (const float*)d_in[i]; break;
            default: break;
        }
    }
    float* out = (float*)d_out;

    const int smem_bytes = (4 * BM * LDT) * (int)sizeof(__half)
                         + 16 * (int)sizeof(float);
    cudaFuncSetAttribute(nf4_gemm_kernel,
                         cudaFuncAttributeMaxDynamicSharedMemorySize, smem_bytes);

    dim3 grid((4096 / BM) * (11008 / BN));   // 2752 CTAs, swizzled in-kernel
    nf4_gemm_kernel<<<grid, THREADS, smem_bytes>>>(x, wp, amax, bias, out);
}

// round 6
// speedup vs baseline: 1.5262x; 1.5262x over previous
#include <cuda_runtime.h>
#include <cuda_fp16.h>
#include <cstdint>

// NF4 linear, 3-kernel plan (mma.sync path; tcgen05 not compilable on this
// harness's compute_103 PTX target):
//   1) convert X fp32 -> fp16 scratch
//   2) dequantize W (nibbles * absmax) -> fp16 scratch
//   3) GEMM: out = fp16(XH @ WDQ^T) + fp16(bias), emitted fp32
// M=4096, K=4096, N=11008. GEMM tiles: BM=BN=128, BK=64, 4 warps @ 64x64.

typedef unsigned int u32;

#define BM 128
#define BN 128
#define BK 64
#define LDT 72            // halfs per smem row (144B, 16B-aligned)
#define THREADS 128
#define KDIM 4096
#define NOUT 11008

__device__ __half XH[4096u * 4096u];     // 32 MB scratch
__device__ __half WDQ[11008u * 4096u];   // 90 MB scratch

__constant__ float c_nf4[16] = {
    -1.0f, -0.6961928009986877f, -0.5250730514526367f, -0.39491748809814453f,
    -0.28444138169288635f, -0.18477343022823334f, -0.09105003625154495f, 0.0f,
    0.07958029955625534f, 0.16093020141124725f, 0.24611230194568634f,
    0.33791524171829224f, 0.44070982933044434f, 0.5626170039176941f,
    0.8072066307067871f, 1.0f};

__device__ __forceinline__ void cp16(u32 dst, const void* src) {
    asm volatile("cp.async.cg.shared.global [%0], [%1], 16;\n"
                 :: "r"(dst), "l"(src) : "memory");
}
#define CP_COMMIT() asm volatile("cp.async.commit_group;\n" ::: "memory")
template <int N> __device__ __forceinline__ void cp_wait() {
    asm volatile("cp.async.wait_group %0;\n" :: "n"(N) : "memory");
}

// ---------------- prep kernels ----------------
__global__ __launch_bounds__(256) void convert_x_kernel(const float* __restrict__ X) {
    int t = blockIdx.x * 256 + threadIdx.x;              // 8 floats / thread
    const float4* src = (const float4*)X + (size_t)t * 2;
    float4 a = src[0], b = src[1];
    __half2 h0 = __floats2half2_rn(a.x, a.y), h1 = __floats2half2_rn(a.z, a.w);
    __half2 h2 = __floats2half2_rn(b.x, b.y), h3 = __floats2half2_rn(b.z, b.w);
    uint4 o;
    o.x = *(u32*)&h0; o.y = *(u32*)&h1; o.z = *(u32*)&h2; o.w = *(u32*)&h3;
    *((uint4*)XH + t) = o;
}

__global__ __launch_bounds__(256) void dequant_w_kernel(const int* __restrict__ WP,
                                                        const float* __restrict__ AM) {
    __shared__ float tab[16];
    if (threadIdx.x < 16) tab[threadIdx.x] = c_nf4[threadIdx.x];
    __syncthreads();
    int t = blockIdx.x * 256 + threadIdx.x;              // 4 code-ints / thread
    int g = t * 4;
    int n = g >> 11;                                     // 2048 ints per W row
    int i = g & 2047;
    float s = AM[(size_t)n * 64 + (i >> 5)];             // 32 ints = one 64-elem block
    int4 v = *(const int4*)(WP + (size_t)n * 2048 + i);
    int vv[4] = {v.x, v.y, v.z, v.w};
    u32 o[4];
    #pragma unroll
    for (int j = 0; j < 4; j++) {                        // hi nibble = even elem
        __half2 h = __floats2half2_rn(tab[(vv[j] >> 4) & 15] * s,
                                      tab[vv[j] & 15] * s);
        o[j] = *(u32*)&h;
    }
    uint4 w; w.x = o[0]; w.y = o[1]; w.z = o[2]; w.w = o[3];
    *(uint4*)(WDQ + (size_t)n * 4096 + i * 2) = w;
}

// ---------------- GEMM ----------------
#define ABYTES (BM * LDT * 2)              // 18432
#define SMEM_BYTES (4 * ABYTES)            // A0 A1 B0 B1 = 73728

__global__ __launch_bounds__(THREADS, 2)
void nf4_mma_gemm(const float* __restrict__ BIAS, float* __restrict__ OUT)
{
    constexpr int STEPS = KDIM / BK;       // 64
    constexpr int NB = NOUT / BN;          // 86
    constexpr int GRPM = 16;               // m-tiles per swizzle group

    extern __shared__ __half smem[];
    __half* As = smem;                     // [2][BM*LDT]
    __half* Bs = smem + 2 * BM * LDT;      // [2][BM*LDT]

    const int tid = threadIdx.x;
    const int lane = tid & 31;
    const int wid = tid >> 5;
    const int wm = wid >> 1;               // 0..1 (64-row warp tile)
    const int wn = wid & 1;                // 0..1 (64-col warp tile)

    // swizzle: groups of 16 m-tiles sweep all N -> 16MB X slab L2-resident
    const int bid = blockIdx.x;
    const int g = bid / (GRPM * NB), r = bid % (GRPM * NB);
    const int bm = g * GRPM + (r % GRPM), bn = r / GRPM;
    const int mBase = bm * BM, nBase = bn * BN;

    float acc[4][8][4];
    #pragma unroll
    for (int m = 0; m < 4; m++)
        #pragma unroll
        for (int n = 0; n < 8; n++)
            #pragma unroll
            for (int q = 0; q < 4; q++) acc[m][n][q] = 0.f;

    const u32 sAs = (u32)__cvta_generic_to_shared(As);
    const u32 sBs = (u32)__cvta_generic_to_shared(Bs);
    const int prow = tid >> 3;             // 0..15 (row stride 16 per q)
    const int pcol = tid & 7;              // 16B chunk

    auto prefetch = [&](int kt, int buf) {
        const int k0 = kt * BK;
        const u32 ab = sAs + buf * ABYTES;
        const u32 bb = sBs + buf * ABYTES;
        #pragma unroll
        for (int q = 0; q < 8; q++) {
            int row = prow + q * 16;
            cp16(ab + row * (LDT * 2) + pcol * 16,
                 XH + (size_t)(mBase + row) * KDIM + k0 + pcol * 8);
        }
        #pragma unroll
        for (int q = 0; q < 8; q++) {
            int row = prow + q * 16;
            cp16(bb + row * (LDT * 2) + pcol * 16,
                 WDQ + (size_t)(nBase + row) * KDIM + k0 + pcol * 8);
        }
        CP_COMMIT();
    };

    prefetch(0, 0);
    for (int kt = 0; kt < STEPS; kt++) {
        const int buf = kt & 1;
        if (kt + 1 < STEPS) { prefetch(kt + 1, buf ^ 1); cp_wait<1>(); }
        else                { cp_wait<0>(); }
        __syncthreads();

        const __half* Ab = As + buf * BM * LDT;
        const __half* Bb = Bs + buf * BM * LDT;
        #pragma unroll
        for (int kk = 0; kk < BK / 16; kk++) {
            u32 af[4][4];
            #pragma unroll
            for (int m = 0; m < 4; m++) {
                const __half* p = Ab + (wm * 64 + m * 16 + (lane & 15)) * LDT
                                     + kk * 16 + (lane >> 4) * 8;
                u32 addr = (u32)__cvta_generic_to_shared(p);
                asm volatile(
                    "ldmatrix.sync.aligned.m8n8.x4.shared.b16 {%0,%1,%2,%3}, [%4];\n"
                    : "=r"(af[m][0]), "=r"(af[m][1]), "=r"(af[m][2]), "=r"(af[m][3])
                    : "r"(addr));
            }
            u32 bf[8][2];
            #pragma unroll
            for (int np = 0; np < 4; np++) {
                int grp = lane >> 3;
                const __half* p = Bb + (wn * 64 + np * 16 + (grp >> 1) * 8 + (lane & 7)) * LDT
                                     + kk * 16 + (grp & 1) * 8;
                u32 addr = (u32)__cvta_generic_to_shared(p);
                u32 q0, q1, q2, q3;
                asm volatile(
                    "ldmatrix.sync.aligned.m8n8.x4.shared.b16 {%0,%1,%2,%3}, [%4];\n"
                    : "=r"(q0), "=r"(q1), "=r"(q2), "=r"(q3)
                    : "r"(addr));
                bf[np * 2][0] = q0;     bf[np * 2][1] = q1;
                bf[np * 2 + 1][0] = q2; bf[np * 2 + 1][1] = q3;
            }
            #pragma unroll
            for (int m = 0; m < 4; m++)
                #pragma unroll
                for (int n = 0; n < 8; n++)
                    asm volatile(
                        "mma.sync.aligned.m16n8k16.row.col.f32.f16.f16.f32 "
                        "{%0,%1,%2,%3}, {%4,%5,%6,%7}, {%8,%9}, {%0,%1,%2,%3};\n"
                        : "+f"(acc[m][n][0]), "+f"(acc[m][n][1]),
                          "+f"(acc[m][n][2]), "+f"(acc[m][n][3])
                        : "r"(af[m][0]), "r"(af[m][1]), "r"(af[m][2]), "r"(af[m][3]),
                          "r"(bf[n][0]), "r"(bf[n][1]));
        }
        __syncthreads();   // compute done before buf is refilled next iter
    }

    // epilogue: emulate fp16(dot)+fp16(bias) rounding, emit fp32
    #pragma unroll
    for (int n = 0; n < 8; n++) {
        int colBase = nBase + wn * 64 + n * 8 + 2 * (lane & 3);
        float b0 = __half2float(__float2half_rn(BIAS[colBase]));
        float b1 = __half2float(__float2half_rn(BIAS[colBase + 1]));
        #pragma unroll
        for (int m = 0; m < 4; m++) {
            int row0 = mBase + wm * 64 + m * 16 + (lane >> 2);
            float o00 = __half2float(__float2half_rn(
                          __half2float(__float2half_rn(acc[m][n][0])) + b0));
            float o01 = __half2float(__float2half_rn(
                          __half2float(__float2half_rn(acc[m][n][1])) + b1));
            float o10 = __half2float(__float2half_rn(
                          __half2float(__float2half_rn(acc[m][n][2])) + b0));
            float o11 = __half2float(__float2half_rn(
                          __half2float(__float2half_rn(acc[m][n][3])) + b1));
            *(float2*)(OUT + (size_t)row0 * NOUT + colBase) = make_float2(o00, o01);
            *(float2*)(OUT + (size_t)(row0 + 8) * NOUT + colBase) = make_float2(o10, o11);
        }
    }
}

extern "C" void kernel_launch(void* const* d_in, const int* in_sizes, int n_in,
                              void* d_out, int out_size)
{
    const float* x    = nullptr;
    const int*   wp   = nullptr;
    const float* amax = nullptr;
    const float* bias = nullptr;
    for (int i = 0; i < n_in; i++) {
        switch (in_sizes[i]) {
            case 16777216: x    = (const float*)d_in[i]; break;
            case 22544384: wp   = (const int*)d_in[i];   break;
            case 704512:   amax = (const float*)d_in[i]; break;
            case 11008:    bias = (const float*)d_in[i]; break;
            default: break;
        }
    }
    float* out = (float*)d_out;

    convert_x_kernel<<<8192, 256>>>(x);
    dequant_w_kernel<<<22016, 256>>>(wp, amax);

    cudaFuncSetAttribute(nf4_mma_gemm,
                         cudaFuncAttributeMaxDynamicSharedMemorySize, SMEM_BYTES);
    nf4_mma_gemm<<<(4096 / BM) * (11008 / BN), THREADS, SMEM_BYTES>>>(bias, out);
}

// round 8
// speedup vs baseline: 1.6329x; 1.0699x over previous
#include <cuda_runtime.h>
#include <cuda_fp16.h>
#include <cstdint>

// NF4 linear, 3-kernel plan (mma.sync path; tcgen05 not available on the
// harness's compute_103 PTX target):
//   1) convert X fp32 -> fp16 scratch
//   2) dequantize W (nibbles * absmax) -> fp16 scratch
//   3) GEMM: out = fp16(XH @ WDQ^T) + fp16(bias), emitted fp32
// M=4096, K=4096, N=11008. GEMM: BM=BN=128, BK=64, 4 warps @ 64x64,
// 3-stage cp.async pipeline, ONE __syncthreads per K-step.
// (Resubmission of R7 — prior round died to a container/broker failure
//  before the kernel ever ran; source is hang-free by construction:
//  uniform cp.async group accounting, unconditional barriers, no spin loops.)

typedef unsigned int u32;

#define BM 128
#define BN 128
#define BK 64
#define LDT 72            // halfs per smem row (144B, 16B-aligned)
#define THREADS 128
#define KDIM 4096
#define NOUT 11008
#define NSTAGE 3

__device__ __half XH[4096u * 4096u];     // 32 MB scratch
__device__ __half WDQ[11008u * 4096u];   // 90 MB scratch

__constant__ float c_nf4[16] = {
    -1.0f, -0.6961928009986877f, -0.5250730514526367f, -0.39491748809814453f,
    -0.28444138169288635f, -0.18477343022823334f, -0.09105003625154495f, 0.0f,
    0.07958029955625534f, 0.16093020141124725f, 0.24611230194568634f,
    0.33791524171829224f, 0.44070982933044434f, 0.5626170039176941f,
    0.8072066307067871f, 1.0f};

__device__ __forceinline__ void cp16(u32 dst, const void* src) {
    asm volatile("cp.async.cg.shared.global [%0], [%1], 16;\n"
                 :: "r"(dst), "l"(src) : "memory");
}
#define CP_COMMIT() asm volatile("cp.async.commit_group;\n" ::: "memory")
template <int N> __device__ __forceinline__ void cp_wait() {
    asm volatile("cp.async.wait_group %0;\n" :: "n"(N) : "memory");
}

// ---------------- prep kernels ----------------
__global__ __launch_bounds__(256) void convert_x_kernel(const float* __restrict__ X) {
    int t = blockIdx.x * 256 + threadIdx.x;              // 8 floats / thread
    const float4* src = (const float4*)X + (size_t)t * 2;
    float4 a = src[0], b = src[1];
    __half2 h0 = __floats2half2_rn(a.x, a.y), h1 = __floats2half2_rn(a.z, a.w);
    __half2 h2 = __floats2half2_rn(b.x, b.y), h3 = __floats2half2_rn(b.z, b.w);
    uint4 o;
    o.x = *(u32*)&h0; o.y = *(u32*)&h1; o.z = *(u32*)&h2; o.w = *(u32*)&h3;
    *((uint4*)XH + t) = o;
}

__global__ __launch_bounds__(256) void dequant_w_kernel(const int* __restrict__ WP,
                                                        const float* __restrict__ AM) {
    __shared__ float tab[16];
    if (threadIdx.x < 16) tab[threadIdx.x] = c_nf4[threadIdx.x];
    __syncthreads();
    int t = blockIdx.x * 256 + threadIdx.x;              // 4 code-ints / thread
    int g = t * 4;
    int n = g >> 11;                                     // 2048 ints per W row
    int i = g & 2047;
    float s = AM[(size_t)n * 64 + (i >> 5)];             // 32 ints = one 64-elem block
    int4 v = *(const int4*)(WP + (size_t)n * 2048 + i);
    int vv[4] = {v.x, v.y, v.z, v.w};
    u32 o[4];
    #pragma unroll
    for (int j = 0; j < 4; j++) {                        // hi nibble = even elem
        __half2 h = __floats2half2_rn(tab[(vv[j] >> 4) & 15] * s,
                                      tab[vv[j] & 15] * s);
        o[j] = *(u32*)&h;
    }
    uint4 w; w.x = o[0]; w.y = o[1]; w.z = o[2]; w.w = o[3];
    *(uint4*)(WDQ + (size_t)n * 4096 + i * 2) = w;
}

// ---------------- GEMM ----------------
#define TILEB (BM * LDT * 2)                   // 18432 bytes (one A or B tile)
#define STAGEB (2 * TILEB)                     // A+B per stage = 36864
#define SMEM_BYTES (NSTAGE * STAGEB)           // 110592

__global__ __launch_bounds__(THREADS, 2)
void nf4_mma_gemm(const float* __restrict__ BIAS, float* __restrict__ OUT)
{
    constexpr int STEPS = KDIM / BK;           // 64
    constexpr int NB = NOUT / BN;              // 86
    constexpr int GRPM = 16;                   // m-tiles per swizzle group

    extern __shared__ __half smem[];

    const int tid = threadIdx.x;
    const int lane = tid & 31;
    const int wid = tid >> 5;
    const int wm = wid >> 1;                   // 0..1 (64-row warp tile)
    const int wn = wid & 1;                    // 0..1 (64-col warp tile)

    // swizzle: groups of 16 m-tiles sweep all N -> 16MB X slab L2-resident
    const int bid = blockIdx.x;
    const int g = bid / (GRPM * NB), r = bid % (GRPM * NB);
    const int bm = g * GRPM + (r % GRPM), bn = r / GRPM;
    const int mBase = bm * BM, nBase = bn * BN;

    float acc[4][8][4];
    #pragma unroll
    for (int m = 0; m < 4; m++)
        #pragma unroll
        for (int n = 0; n < 8; n++)
            #pragma unroll
            for (int q = 0; q < 4; q++) acc[m][n][q] = 0.f;

    const u32 sbase = (u32)__cvta_generic_to_shared(smem);
    const int prow = tid >> 3;                 // 0..15 (row stride 16 per q)
    const int pcol = tid & 7;                  // 16B chunk

    auto prefetch = [&](int kt) {
        const int stage = kt % NSTAGE;
        const int k0 = kt * BK;
        const u32 ab = sbase + stage * STAGEB;
        const u32 bb = ab + TILEB;
        #pragma unroll
        for (int q = 0; q < 8; q++) {
            int row = prow + q * 16;
            cp16(ab + row * (LDT * 2) + pcol * 16,
                 XH + (size_t)(mBase + row) * KDIM + k0 + pcol * 8);
        }
        #pragma unroll
        for (int q = 0; q < 8; q++) {
            int row = prow + q * 16;
            cp16(bb + row * (LDT * 2) + pcol * 16,
                 WDQ + (size_t)(nBase + row) * KDIM + k0 + pcol * 8);
        }
        CP_COMMIT();
    };

    // prologue: stages 0 and 1 in flight
    prefetch(0);
    prefetch(1);

    for (int kt = 0; kt < STEPS; kt++) {
        cp_wait<1>();          // stage kt resident (allow stage kt+1 in flight)
        __syncthreads();       // all warps past compute kt-1; stage kt visible

        // issue copies for kt+2 (reuses stage (kt-1)%3 — safe after the barrier)
        if (kt + 2 < STEPS) prefetch(kt + 2);
        else                CP_COMMIT();       // keep group accounting uniform

        const int stage = kt % NSTAGE;
        const __half* Ab = smem + stage * (STAGEB / 2);
        const __half* Bb = Ab + BM * LDT;
        #pragma unroll
        for (int kk = 0; kk < BK / 16; kk++) {
            u32 af[4][4];
            #pragma unroll
            for (int m = 0; m < 4; m++) {
                const __half* p = Ab + (wm * 64 + m * 16 + (lane & 15)) * LDT
                                     + kk * 16 + (lane >> 4) * 8;
                u32 addr = (u32)__cvta_generic_to_shared(p);
                asm volatile(
                    "ldmatrix.sync.aligned.m8n8.x4.shared.b16 {%0,%1,%2,%3}, [%4];\n"
                    : "=r"(af[m][0]), "=r"(af[m][1]), "=r"(af[m][2]), "=r"(af[m][3])
                    : "r"(addr));
            }
            u32 bf[8][2];
            #pragma unroll
            for (int np = 0; np < 4; np++) {
                int grp = lane >> 3;
                const __half* p = Bb + (wn * 64 + np * 16 + (grp >> 1) * 8 + (lane & 7)) * LDT
                                     + kk * 16 + (grp & 1) * 8;
                u32 addr = (u32)__cvta_generic_to_shared(p);
                u32 q0, q1, q2, q3;
                asm volatile(
                    "ldmatrix.sync.aligned.m8n8.x4.shared.b16 {%0,%1,%2,%3}, [%4];\n"
                    : "=r"(q0), "=r"(q1), "=r"(q2), "=r"(q3)
                    : "r"(addr));
                bf[np * 2][0] = q0;     bf[np * 2][1] = q1;
                bf[np * 2 + 1][0] = q2; bf[np * 2 + 1][1] = q3;
            }
            #pragma unroll
            for (int m = 0; m < 4; m++)
                #pragma unroll
                for (int n = 0; n < 8; n++)
                    asm volatile(
                        "mma.sync.aligned.m16n8k16.row.col.f32.f16.f16.f32 "
                        "{%0,%1,%2,%3}, {%4,%5,%6,%7}, {%8,%9}, {%0,%1,%2,%3};\n"
                        : "+f"(acc[m][n][0]), "+f"(acc[m][n][1]),
                          "+f"(acc[m][n][2]), "+f"(acc[m][n][3])
                        : "r"(af[m][0]), "r"(af[m][1]), "r"(af[m][2]), "r"(af[m][3]),
                          "r"(bf[n][0]), "r"(bf[n][1]));
        }
    }

    // epilogue: emulate fp16(dot)+fp16(bias) rounding, emit fp32
    #pragma unroll
    for (int n = 0; n < 8; n++) {
        int colBase = nBase + wn * 64 + n * 8 + 2 * (lane & 3);
        float b0 = __half2float(__float2half_rn(BIAS[colBase]));
        float b1 = __half2float(__float2half_rn(BIAS[colBase + 1]));
        #pragma unroll
        for (int m = 0; m < 4; m++) {
            int row0 = mBase + wm * 64 + m * 16 + (lane >> 2);
            float o00 = __half2float(__float2half_rn(
                          __half2float(__float2half_rn(acc[m][n][0])) + b0));
            float o01 = __half2float(__float2half_rn(
                          __half2float(__float2half_rn(acc[m][n][1])) + b1));
            float o10 = __half2float(__float2half_rn(
                          __half2float(__float2half_rn(acc[m][n][2])) + b0));
            float o11 = __half2float(__float2half_rn(
                          __half2float(__float2half_rn(acc[m][n][3])) + b1));
            *(float2*)(OUT + (size_t)row0 * NOUT + colBase) = make_float2(o00, o01);
            *(float2*)(OUT + (size_t)(row0 + 8) * NOUT + colBase) = make_float2(o10, o11);
        }
    }
}

extern "C" void kernel_launch(void* const* d_in, const int* in_sizes, int n_in,
                              void* d_out, int out_size)
{
    const float* x    = nullptr;
    const int*   wp   = nullptr;
    const float* amax = nullptr;
    const float* bias = nullptr;
    for (int i = 0; i < n_in; i++) {
        switch (in_sizes[i]) {
            case 16777216: x    = (const float*)d_in[i]; break;
            case 22544384: wp   = (const int*)d_in[i];   break;
            case 704512:   amax = (const float*)d_in[i]; break;
            case 11008:    bias = (const float*)d_in[i]; break;
            default: break;
        }
    }
    float* out = (float*)d_out;

    convert_x_kernel<<<8192, 256>>>(x);
    dequant_w_kernel<<<22016, 256>>>(wp, amax);

    cudaFuncSetAttribute(nf4_mma_gemm,
                         cudaFuncAttributeMaxDynamicSharedMemorySize, SMEM_BYTES);
    nf4_mma_gemm<<<(4096 / BM) * (11008 / BN), THREADS, SMEM_BYTES>>>(bias, out);
}

// round 9
// speedup vs baseline: 1.6338x; 1.0006x over previous
#include <cuda_runtime.h>
#include <cuda_fp16.h>
#include <cstdint>

// NF4 linear, 3-kernel plan (mma.sync path; tcgen05 unavailable on compute_103):
//   1) convert X fp32 -> fp16 scratch
//   2) dequantize W (nibbles * absmax) -> fp16 scratch
//   3) GEMM: out = fp16(XH @ WDQ^T) + fp16(bias), emitted fp32
// GEMM: BM=BN=128, BK=64, 4 warps @ 64x64, 3-stage cp.async pipeline,
// ONE __syncthreads per K-step, register-fragment double buffering across kk.

typedef unsigned int u32;

#define BM 128
#define BN 128
#define BK 64
#define LDT 72            // halfs per smem row (144B, 16B-aligned)
#define THREADS 128
#define KDIM 4096
#define NOUT 11008
#define NSTAGE 3

__device__ __half XH[4096u * 4096u];     // 32 MB scratch
__device__ __half WDQ[11008u * 4096u];   // 90 MB scratch

__constant__ float c_nf4[16] = {
    -1.0f, -0.6961928009986877f, -0.5250730514526367f, -0.39491748809814453f,
    -0.28444138169288635f, -0.18477343022823334f, -0.09105003625154495f, 0.0f,
    0.07958029955625534f, 0.16093020141124725f, 0.24611230194568634f,
    0.33791524171829224f, 0.44070982933044434f, 0.5626170039176941f,
    0.8072066307067871f, 1.0f};

__device__ __forceinline__ void cp16(u32 dst, const void* src) {
    asm volatile("cp.async.cg.shared.global [%0], [%1], 16;\n"
                 :: "r"(dst), "l"(src) : "memory");
}
#define CP_COMMIT() asm volatile("cp.async.commit_group;\n" ::: "memory")
template <int N> __device__ __forceinline__ void cp_wait() {
    asm volatile("cp.async.wait_group %0;\n" :: "n"(N) : "memory");
}

// ---------------- prep kernels ----------------
__global__ __launch_bounds__(256) void convert_x_kernel(const float* __restrict__ X) {
    int t = blockIdx.x * 256 + threadIdx.x;              // 8 floats / thread
    const float4* src = (const float4*)X + (size_t)t * 2;
    float4 a = src[0], b = src[1];
    __half2 h0 = __floats2half2_rn(a.x, a.y), h1 = __floats2half2_rn(a.z, a.w);
    __half2 h2 = __floats2half2_rn(b.x, b.y), h3 = __floats2half2_rn(b.z, b.w);
    uint4 o;
    o.x = *(u32*)&h0; o.y = *(u32*)&h1; o.z = *(u32*)&h2; o.w = *(u32*)&h3;
    *((uint4*)XH + t) = o;
}

__global__ __launch_bounds__(256) void dequant_w_kernel(const int* __restrict__ WP,
                                                        const float* __restrict__ AM) {
    __shared__ float tab[16];
    if (threadIdx.x < 16) tab[threadIdx.x] = c_nf4[threadIdx.x];
    __syncthreads();
    int t = blockIdx.x * 256 + threadIdx.x;              // 4 code-ints / thread
    int g = t * 4;
    int n = g >> 11;                                     // 2048 ints per W row
    int i = g & 2047;
    float s = AM[(size_t)n * 64 + (i >> 5)];             // 32 ints = one 64-elem block
    int4 v = *(const int4*)(WP + (size_t)n * 2048 + i);
    int vv[4] = {v.x, v.y, v.z, v.w};
    u32 o[4];
    #pragma unroll
    for (int j = 0; j < 4; j++) {                        // hi nibble = even elem
        __half2 h = __floats2half2_rn(tab[(vv[j] >> 4) & 15] * s,
                                      tab[vv[j] & 15] * s);
        o[j] = *(u32*)&h;
    }
    uint4 w; w.x = o[0]; w.y = o[1]; w.z = o[2]; w.w = o[3];
    *(uint4*)(WDQ + (size_t)n * 4096 + i * 2) = w;
}

// ---------------- GEMM ----------------
#define TILEB (BM * LDT * 2)                   // 18432 bytes (one A or B tile)
#define STAGEB (2 * TILEB)                     // A+B per stage = 36864
#define SMEM_BYTES (NSTAGE * STAGEB)           // 110592

__global__ __launch_bounds__(THREADS, 2)
void nf4_mma_gemm(const float* __restrict__ BIAS, float* __restrict__ OUT)
{
    constexpr int STEPS = KDIM / BK;           // 64
    constexpr int NB = NOUT / BN;              // 86
    constexpr int GRPM = 16;                   // m-tiles per swizzle group

    extern __shared__ __half smem[];

    const int tid = threadIdx.x;
    const int lane = tid & 31;
    const int wid = tid >> 5;
    const int wm = wid >> 1;                   // 0..1 (64-row warp tile)
    const int wn = wid & 1;                    // 0..1 (64-col warp tile)

    // swizzle: groups of 16 m-tiles sweep all N -> 16MB X slab L2-resident
    const int bid = blockIdx.x;
    const int g = bid / (GRPM * NB), r = bid % (GRPM * NB);
    const int bm = g * GRPM + (r % GRPM), bn = r / GRPM;
    const int mBase = bm * BM, nBase = bn * BN;

    float acc[4][8][4];
    #pragma unroll
    for (int m = 0; m < 4; m++)
        #pragma unroll
        for (int n = 0; n < 8; n++)
            #pragma unroll
            for (int q = 0; q < 4; q++) acc[m][n][q] = 0.f;

    const u32 sbase = (u32)__cvta_generic_to_shared(smem);
    const int prow = tid >> 3;                 // 0..15 (row stride 16 per q)
    const int pcol = tid & 7;                  // 16B chunk

    auto prefetch = [&](int kt) {
        const int stage = kt % NSTAGE;
        const int k0 = kt * BK;
        const u32 ab = sbase + stage * STAGEB;
        const u32 bb = ab + TILEB;
        #pragma unroll
        for (int q = 0; q < 8; q++) {
            int row = prow + q * 16;
            cp16(ab + row * (LDT * 2) + pcol * 16,
                 XH + (size_t)(mBase + row) * KDIM + k0 + pcol * 8);
        }
        #pragma unroll
        for (int q = 0; q < 8; q++) {
            int row = prow + q * 16;
            cp16(bb + row * (LDT * 2) + pcol * 16,
                 WDQ + (size_t)(nBase + row) * KDIM + k0 + pcol * 8);
        }
        CP_COMMIT();
    };

    // register fragment double buffers
    u32 af[2][4][4];
    u32 bf[2][8][2];

    auto load_frags = [&](const __half* Ab, const __half* Bb, int kk, int slot) {
        #pragma unroll
        for (int m = 0; m < 4; m++) {
            const __half* p = Ab + (wm * 64 + m * 16 + (lane & 15)) * LDT
                                 + kk * 16 + (lane >> 4) * 8;
            u32 addr = (u32)__cvta_generic_to_shared(p);
            asm volatile(
                "ldmatrix.sync.aligned.m8n8.x4.shared.b16 {%0,%1,%2,%3}, [%4];\n"
                : "=r"(af[slot][m][0]), "=r"(af[slot][m][1]),
                  "=r"(af[slot][m][2]), "=r"(af[slot][m][3])
                : "r"(addr));
        }
        #pragma unroll
        for (int np = 0; np < 4; np++) {
            int grp = lane >> 3;
            const __half* p = Bb + (wn * 64 + np * 16 + (grp >> 1) * 8 + (lane & 7)) * LDT
                                 + kk * 16 + (grp & 1) * 8;
            u32 addr = (u32)__cvta_generic_to_shared(p);
            u32 q0, q1, q2, q3;
            asm volatile(
                "ldmatrix.sync.aligned.m8n8.x4.shared.b16 {%0,%1,%2,%3}, [%4];\n"
                : "=r"(q0), "=r"(q1), "=r"(q2), "=r"(q3)
                : "r"(addr));
            bf[slot][np * 2][0] = q0;     bf[slot][np * 2][1] = q1;
            bf[slot][np * 2 + 1][0] = q2; bf[slot][np * 2 + 1][1] = q3;
        }
    };

    // prologue: stages 0 and 1 in flight
    prefetch(0);
    prefetch(1);

    for (int kt = 0; kt < STEPS; kt++) {
        cp_wait<1>();          // stage kt resident (stage kt+1 may still fly)
        __syncthreads();       // all warps past compute kt-1; stage kt visible

        // issue copies for kt+2 (reuses stage (kt-1)%3 — safe after the barrier)
        if (kt + 2 < STEPS) prefetch(kt + 2);
        else                CP_COMMIT();       // keep group accounting uniform

        const int stage = kt % NSTAGE;
        const __half* Ab = smem + stage * (STAGEB / 2);
        const __half* Bb = Ab + BM * LDT;

        load_frags(Ab, Bb, 0, 0);              // prime kk=0
        #pragma unroll
        for (int kk = 0; kk < BK / 16; kk++) {
            const int cur = kk & 1;
            if (kk + 1 < BK / 16) load_frags(Ab, Bb, kk + 1, cur ^ 1);
            #pragma unroll
            for (int m = 0; m < 4; m++)
                #pragma unroll
                for (int n = 0; n < 8; n++)
                    asm volatile(
                        "mma.sync.aligned.m16n8k16.row.col.f32.f16.f16.f32 "
                        "{%0,%1,%2,%3}, {%4,%5,%6,%7}, {%8,%9}, {%0,%1,%2,%3};\n"
                        : "+f"(acc[m][n][0]), "+f"(acc[m][n][1]),
                          "+f"(acc[m][n][2]), "+f"(acc[m][n][3])
                        : "r"(af[cur][m][0]), "r"(af[cur][m][1]),
                          "r"(af[cur][m][2]), "r"(af[cur][m][3]),
                          "r"(bf[cur][n][0]), "r"(bf[cur][n][1]));
        }
    }

    // epilogue: emulate fp16(dot)+fp16(bias) rounding, emit fp32
    #pragma unroll
    for (int n = 0; n < 8; n++) {
        int colBase = nBase + wn * 64 + n * 8 + 2 * (lane & 3);
        float b0 = __half2float(__float2half_rn(BIAS[colBase]));
        float b1 = __half2float(__float2half_rn(BIAS[colBase + 1]));
        #pragma unroll
        for (int m = 0; m < 4; m++) {
            int row0 = mBase + wm * 64 + m * 16 + (lane >> 2);
            float o00 = __half2float(__float2half_rn(
                          __half2float(__float2half_rn(acc[m][n][0])) + b0));
            float o01 = __half2float(__float2half_rn(
                          __half2float(__float2half_rn(acc[m][n][1])) + b1));
            float o10 = __half2float(__float2half_rn(
                          __half2float(__float2half_rn(acc[m][n][2])) + b0));
            float o11 = __half2float(__float2half_rn(
                          __half2float(__float2half_rn(acc[m][n][3])) + b1));
            *(float2*)(OUT + (size_t)row0 * NOUT + colBase) = make_float2(o00, o01);
            *(float2*)(OUT + (size_t)(row0 + 8) * NOUT + colBase) = make_float2(o10, o11);
        }
    }
}

extern "C" void kernel_launch(void* const* d_in, const int* in_sizes, int n_in,
                              void* d_out, int out_size)
{
    const float* x    = nullptr;
    const int*   wp   = nullptr;
    const float* amax = nullptr;
    const float* bias = nullptr;
    for (int i = 0; i < n_in; i++) {
        switch (in_sizes[i]) {
            case 16777216: x    = (const float*)d_in[i]; break;
            case 22544384: wp   = (const int*)d_in[i];   break;
            case 704512:   amax = (const float*)d_in[i]; break;
            case 11008:    bias = (const float*)d_in[i]; break;
            default: break;
        }
    }
    float* out = (float*)d_out;

    convert_x_kernel<<<8192, 256>>>(x);
    dequant_w_kernel<<<22016, 256>>>(wp, amax);

    cudaFuncSetAttribute(nf4_mma_gemm,
                         cudaFuncAttributeMaxDynamicSharedMemorySize, SMEM_BYTES);
    nf4_mma_gemm<<<(4096 / BM) * (11008 / BN), THREADS, SMEM_BYTES>>>(bias, out);
}

// round 10
// speedup vs baseline: 1.8190x; 1.1134x over previous
#include <cuda_runtime.h>
#include <cuda_fp16.h>
#include <cstdint>

// NF4 linear, 3-kernel plan (mma.sync path; tcgen05 unavailable on compute_103):
//   1) convert X fp32 -> fp16 scratch
//   2) dequantize W (nibbles * absmax) -> fp16 scratch
//   3) GEMM: out = fp16(XH @ WDQ^T) + fp16(bias), emitted fp32
// GEMM: BM=BN=128, BK=64, 4 warps @ 64x64, 2-stage cp.async pipeline with
// ONE __syncthreads per K-step, 3 CTAs/SM (12 warps -> 3 per SMSP).

typedef unsigned int u32;

#define BM 128
#define BN 128
#define BK 64
#define LDT 72            // halfs per smem row (144B, 16B-aligned)
#define THREADS 128
#define KDIM 4096
#define NOUT 11008
#define NSTAGE 2

__device__ __half XH[4096u * 4096u];     // 32 MB scratch
__device__ __half WDQ[11008u * 4096u];   // 90 MB scratch

__constant__ float c_nf4[16] = {
    -1.0f, -0.6961928009986877f, -0.5250730514526367f, -0.39491748809814453f,
    -0.28444138169288635f, -0.18477343022823334f, -0.09105003625154495f, 0.0f,
    0.07958029955625534f, 0.16093020141124725f, 0.24611230194568634f,
    0.33791524171829224f, 0.44070982933044434f, 0.5626170039176941f,
    0.8072066307067871f, 1.0f};

__device__ __forceinline__ void cp16(u32 dst, const void* src) {
    asm volatile("cp.async.cg.shared.global [%0], [%1], 16;\n"
                 :: "r"(dst), "l"(src) : "memory");
}
#define CP_COMMIT() asm volatile("cp.async.commit_group;\n" ::: "memory")
template <int N> __device__ __forceinline__ void cp_wait() {
    asm volatile("cp.async.wait_group %0;\n" :: "n"(N) : "memory");
}

// ---------------- prep kernels ----------------
__global__ __launch_bounds__(256) void convert_x_kernel(const float* __restrict__ X) {
    int t = blockIdx.x * 256 + threadIdx.x;              // 8 floats / thread
    const float4* src = (const float4*)X + (size_t)t * 2;
    float4 a = src[0], b = src[1];
    __half2 h0 = __floats2half2_rn(a.x, a.y), h1 = __floats2half2_rn(a.z, a.w);
    __half2 h2 = __floats2half2_rn(b.x, b.y), h3 = __floats2half2_rn(b.z, b.w);
    uint4 o;
    o.x = *(u32*)&h0; o.y = *(u32*)&h1; o.z = *(u32*)&h2; o.w = *(u32*)&h3;
    *((uint4*)XH + t) = o;
}

__global__ __launch_bounds__(256) void dequant_w_kernel(const int* __restrict__ WP,
                                                        const float* __restrict__ AM) {
    __shared__ float tab[16];
    if (threadIdx.x < 16) tab[threadIdx.x] = c_nf4[threadIdx.x];
    __syncthreads();
    int t = blockIdx.x * 256 + threadIdx.x;              // 4 code-ints / thread
    int g = t * 4;
    int n = g >> 11;                                     // 2048 ints per W row
    int i = g & 2047;
    float s = AM[(size_t)n * 64 + (i >> 5)];             // 32 ints = one 64-elem block
    int4 v = *(const int4*)(WP + (size_t)n * 2048 + i);
    int vv[4] = {v.x, v.y, v.z, v.w};
    u32 o[4];
    #pragma unroll
    for (int j = 0; j < 4; j++) {                        // hi nibble = even elem
        __half2 h = __floats2half2_rn(tab[(vv[j] >> 4) & 15] * s,
                                      tab[vv[j] & 15] * s);
        o[j] = *(u32*)&h;
    }
    uint4 w; w.x = o[0]; w.y = o[1]; w.z = o[2]; w.w = o[3];
    *(uint4*)(WDQ + (size_t)n * 4096 + i * 2) = w;
}

// ---------------- GEMM ----------------
#define TILEB (BM * LDT * 2)                   // 18432 bytes (one A or B tile)
#define STAGEB (2 * TILEB)                     // A+B per stage = 36864
#define SMEM_BYTES (NSTAGE * STAGEB)           // 73728

__global__ __launch_bounds__(THREADS, 3)
void nf4_mma_gemm(const float* __restrict__ BIAS, float* __restrict__ OUT)
{
    constexpr int STEPS = KDIM / BK;           // 64
    constexpr int NB = NOUT / BN;              // 86
    constexpr int GRPM = 16;                   // m-tiles per swizzle group

    extern __shared__ __half smem[];

    const int tid = threadIdx.x;
    const int lane = tid & 31;
    const int wid = tid >> 5;
    const int wm = wid >> 1;                   // 0..1 (64-row warp tile)
    const int wn = wid & 1;                    // 0..1 (64-col warp tile)

    // swizzle: groups of 16 m-tiles sweep all N -> 16MB X slab L2-resident
    const int bid = blockIdx.x;
    const int g = bid / (GRPM * NB), r = bid % (GRPM * NB);
    const int bm = g * GRPM + (r % GRPM), bn = r / GRPM;
    const int mBase = bm * BM, nBase = bn * BN;

    float acc[4][8][4];
    #pragma unroll
    for (int m = 0; m < 4; m++)
        #pragma unroll
        for (int n = 0; n < 8; n++)
            #pragma unroll
            for (int q = 0; q < 4; q++) acc[m][n][q] = 0.f;

    const u32 sbase = (u32)__cvta_generic_to_shared(smem);
    const int prow = tid >> 3;                 // 0..15 (row stride 16 per q)
    const int pcol = tid & 7;                  // 16B chunk

    auto prefetch = [&](int kt) {
        const int stage = kt & 1;
        const int k0 = kt * BK;
        const u32 ab = sbase + stage * STAGEB;
        const u32 bb = ab + TILEB;
        #pragma unroll
        for (int q = 0; q < 8; q++) {
            int row = prow + q * 16;
            cp16(ab + row * (LDT * 2) + pcol * 16,
                 XH + (size_t)(mBase + row) * KDIM + k0 + pcol * 8);
        }
        #pragma unroll
        for (int q = 0; q < 8; q++) {
            int row = prow + q * 16;
            cp16(bb + row * (LDT * 2) + pcol * 16,
                 WDQ + (size_t)(nBase + row) * KDIM + k0 + pcol * 8);
        }
        CP_COMMIT();
    };

    prefetch(0);   // stage 0 in flight

    for (int kt = 0; kt < STEPS; kt++) {
        cp_wait<0>();          // stage kt resident
        __syncthreads();       // all warps done computing kt-1 (stage (kt+1)&1 free)

        // copy for kt+1 overlaps compute of kt (single barrier per iteration)
        if (kt + 1 < STEPS) prefetch(kt + 1);
        else                CP_COMMIT();       // uniform group accounting

        const __half* Ab = smem + (kt & 1) * (STAGEB / 2);
        const __half* Bb = Ab + BM * LDT;
        #pragma unroll
        for (int kk = 0; kk < BK / 16; kk++) {
            u32 af[4][4];
            #pragma unroll
            for (int m = 0; m < 4; m++) {
                const __half* p = Ab + (wm * 64 + m * 16 + (lane & 15)) * LDT
                                     + kk * 16 + (lane >> 4) * 8;
                u32 addr = (u32)__cvta_generic_to_shared(p);
                asm volatile(
                    "ldmatrix.sync.aligned.m8n8.x4.shared.b16 {%0,%1,%2,%3}, [%4];\n"
                    : "=r"(af[m][0]), "=r"(af[m][1]), "=r"(af[m][2]), "=r"(af[m][3])
                    : "r"(addr));
            }
            u32 bf[8][2];
            #pragma unroll
            for (int np = 0; np < 4; np++) {
                int grp = lane >> 3;
                const __half* p = Bb + (wn * 64 + np * 16 + (grp >> 1) * 8 + (lane & 7)) * LDT
                                     + kk * 16 + (grp & 1) * 8;
                u32 addr = (u32)__cvta_generic_to_shared(p);
                u32 q0, q1, q2, q3;
                asm volatile(
                    "ldmatrix.sync.aligned.m8n8.x4.shared.b16 {%0,%1,%2,%3}, [%4];\n"
                    : "=r"(q0), "=r"(q1), "=r"(q2), "=r"(q3)
                    : "r"(addr));
                bf[np * 2][0] = q0;     bf[np * 2][1] = q1;
                bf[np * 2 + 1][0] = q2; bf[np * 2 + 1][1] = q3;
            }
            #pragma unroll
            for (int m = 0; m < 4; m++)
                #pragma unroll
                for (int n = 0; n < 8; n++)
                    asm volatile(
                        "mma.sync.aligned.m16n8k16.row.col.f32.f16.f16.f32 "
                        "{%0,%1,%2,%3}, {%4,%5,%6,%7}, {%8,%9}, {%0,%1,%2,%3};\n"
                        : "+f"(acc[m][n][0]), "+f"(acc[m][n][1]),
                          "+f"(acc[m][n][2]), "+f"(acc[m][n][3])
                        : "r"(af[m][0]), "r"(af[m][1]), "r"(af[m][2]), "r"(af[m][3]),
                          "r"(bf[n][0]), "r"(bf[n][1]));
        }
    }

    // epilogue: emulate fp16(dot)+fp16(bias) rounding, emit fp32
    #pragma unroll
    for (int n = 0; n < 8; n++) {
        int colBase = nBase + wn * 64 + n * 8 + 2 * (lane & 3);
        float b0 = __half2float(__float2half_rn(BIAS[colBase]));
        float b1 = __half2float(__float2half_rn(BIAS[colBase + 1]));
        #pragma unroll
        for (int m = 0; m < 4; m++) {
            int row0 = mBase + wm * 64 + m * 16 + (lane >> 2);
            float o00 = __half2float(__float2half_rn(
                          __half2float(__float2half_rn(acc[m][n][0])) + b0));
            float o01 = __half2float(__float2half_rn(
                          __half2float(__float2half_rn(acc[m][n][1])) + b1));
            float o10 = __half2float(__float2half_rn(
                          __half2float(__float2half_rn(acc[m][n][2])) + b0));
            float o11 = __half2float(__float2half_rn(
                          __half2float(__float2half_rn(acc[m][n][3])) + b1));
            *(float2*)(OUT + (size_t)row0 * NOUT + colBase) = make_float2(o00, o01);
            *(float2*)(OUT + (size_t)(row0 + 8) * NOUT + colBase) = make_float2(o10, o11);
        }
    }
}

extern "C" void kernel_launch(void* const* d_in, const int* in_sizes, int n_in,
                              void* d_out, int out_size)
{
    const float* x    = nullptr;
    const int*   wp   = nullptr;
    const float* amax = nullptr;
    const float* bias = nullptr;
    for (int i = 0; i < n_in; i++) {
        switch (in_sizes[i]) {
            case 16777216: x    = (const float*)d_in[i]; break;
            case 22544384: wp   = (const int*)d_in[i];   break;
            case 704512:   amax = (const float*)d_in[i]; break;
            case 11008:    bias = (const float*)d_in[i]; break;
            default: break;
        }
    }
    float* out = (float*)d_out;

    convert_x_kernel<<<8192, 256>>>(x);
    dequant_w_kernel<<<22016, 256>>>(wp, amax);

    cudaFuncSetAttribute(nf4_mma_gemm,
                         cudaFuncAttributeMaxDynamicSharedMemorySize, SMEM_BYTES);
    nf4_mma_gemm<<<(4096 / BM) * (11008 / BN), THREADS, SMEM_BYTES>>>(bias, out);
}

// round 11
// speedup vs baseline: 2.2490x; 1.2364x over previous
#include <cuda_runtime.h>
#include <cuda_fp16.h>
#include <cstdint>

// NF4 linear, 3-kernel plan (mma.sync path; tcgen05 unavailable on compute_103):
//   1) convert X fp32 -> fp16, TILE-MAJOR + PRE-SWIZZLED scratch
//   2) dequantize W -> fp16, TILE-MAJOR + PRE-SWIZZLED scratch
//   3) GEMM: out = fp16(XT @ WT^T) + fp16(bias), emitted fp32
// GEMM: BM=BN=128, BK=64, 4 warps @ 64x64, 2-stage pipeline where each stage
// is filled by TWO cp.async.bulk (16KB each) issued by ONE thread, completion
// tracked by mbarrier expect_tx. 3 CTAs/SM.

typedef unsigned int u32;

#define BM 128
#define BN 128
#define BK 64
#define THREADS 128
#define KDIM 4096
#define NOUT 11008
#define TILE_BYTES 16384                       // 128 rows x 128B (64 halfs)

// tile-major pre-swizzled scratch
__device__ __align__(1024) unsigned char XT[32u * 64u * 16384u];   // 32 MB
__device__ __align__(1024) unsigned char WT[86u * 64u * 16384u];   // 90 MB

__constant__ float c_nf4[16] = {
    -1.0f, -0.6961928009986877f, -0.5250730514526367f, -0.39491748809814453f,
    -0.28444138169288635f, -0.18477343022823334f, -0.09105003625154495f, 0.0f,
    0.07958029955625534f, 0.16093020141124725f, 0.24611230194568634f,
    0.33791524171829224f, 0.44070982933044434f, 0.5626170039176941f,
    0.8072066307067871f, 1.0f};

__device__ __forceinline__ u32 sw128(u32 off) { return off ^ ((off >> 3) & 0x70); }

#define MBAR_INIT(a, c) \
    asm volatile("mbarrier.init.shared.b64 [%0], %1;" :: "r"(a), "r"(c) : "memory")
#define MBAR_EXPECT_TX(a, tx) \
    asm volatile("mbarrier.arrive.expect_tx.shared.b64 _, [%0], %1;" \
                 :: "r"(a), "r"(tx) : "memory")
#define MBAR_WAIT(a, par) do {                                                       \
    u32 _mb = (a); u32 _p = (par); u32 _done;                                        \
    asm volatile("{ .reg .pred p; mbarrier.try_wait.parity.shared.b64 p, [%1], %2;"  \
                 " selp.b32 %0,1,0,p; }" : "=r"(_done) : "r"(_mb), "r"(_p) : "memory"); \
    while (!_done) {                                                                 \
        asm volatile("{ .reg .pred p; mbarrier.try_wait.parity.shared.b64 p, [%1], %2;" \
                     " selp.b32 %0,1,0,p; }" : "=r"(_done) : "r"(_mb), "r"(_p) : "memory"); \
    }                                                                                \
} while (0)

__device__ __forceinline__ void bulk_cp(u32 dst, const void* src, u32 bytes, u32 bar) {
    asm volatile(
        "cp.async.bulk.shared::cta.global.mbarrier::complete_tx::bytes "
        "[%0], [%1], %2, [%3];\n"
        :: "r"(dst), "l"(src), "r"(bytes), "r"(bar) : "memory");
}

// ---------------- prep kernels (tile-major, pre-swizzled output) ----------------
// chunk id t -> tile = t>>10 (bm*64+kt), c = t&1023, r = c>>3, j = c&7.
__global__ __launch_bounds__(256) void convert_x_kernel(const float* __restrict__ X) {
    int t = blockIdx.x * 256 + threadIdx.x;        // 2M chunks
    int tile = t >> 10, c = t & 1023;
    int bm = tile >> 6, kt = tile & 63;
    int r = c >> 3, j = c & 7;
    const float* xp = X + (size_t)(bm * 128 + r) * KDIM + kt * 64 + j * 8;
    float4 a = *(const float4*)xp, b = *(const float4*)(xp + 4);
    __half2 h0 = __floats2half2_rn(a.x, a.y), h1 = __floats2half2_rn(a.z, a.w);
    __half2 h2 = __floats2half2_rn(b.x, b.y), h3 = __floats2half2_rn(b.z, b.w);
    uint4 o;
    o.x = *(u32*)&h0; o.y = *(u32*)&h1; o.z = *(u32*)&h2; o.w = *(u32*)&h3;
    *(uint4*)(XT + (size_t)tile * TILE_BYTES + sw128(r * 128 + j * 16)) = o;
}

__global__ __launch_bounds__(256) void dequant_w_kernel(const int* __restrict__ WP,
                                                        const float* __restrict__ AM) {
    __shared__ float tab[16];
    if (threadIdx.x < 16) tab[threadIdx.x] = c_nf4[threadIdx.x];
    __syncthreads();
    int t = blockIdx.x * 256 + threadIdx.x;        // 5.63M chunks
    int tile = t >> 10, c = t & 1023;
    int bn = tile >> 6, kt = tile & 63;
    int r = c >> 3, j = c & 7;
    int n = bn * 128 + r;
    float s = AM[(size_t)n * 64 + kt];             // kt == absmax block index
    int4 v = *(const int4*)(WP + (size_t)n * 2048 + kt * 32 + j * 4);
    int vv[4] = {v.x, v.y, v.z, v.w};
    u32 o[4];
    #pragma unroll
    for (int q = 0; q < 4; q++) {                  // hi nibble = even elem
        __half2 h = __floats2half2_rn(tab[(vv[q] >> 4) & 15] * s,
                                      tab[vv[q] & 15] * s);
        o[q] = *(u32*)&h;
    }
    uint4 w; w.x = o[0]; w.y = o[1]; w.z = o[2]; w.w = o[3];
    *(uint4*)(WT + (size_t)tile * TILE_BYTES + sw128(r * 128 + j * 16)) = w;
}

// ---------------- GEMM ----------------
#define STAGEB (2 * TILE_BYTES)                    // A+B per stage = 32768
#define SMEM_BYTES (1024 + 2 * STAGEB)             // 66560

__global__ __launch_bounds__(THREADS, 3)
void nf4_mma_gemm(const float* __restrict__ BIAS, float* __restrict__ OUT)
{
    constexpr int STEPS = KDIM / BK;               // 64
    constexpr int NB = NOUT / BN;                  // 86
    constexpr int GRPM = 16;                       // m-tiles per swizzle group

    extern __shared__ unsigned char smem[];
    u32 sbase;
    asm("{ .reg .u64 t; cvta.to.shared.u64 t, %1; cvt.u32.u64 %0, t; }"
        : "=r"(sbase) : "l"(smem));
    const u32 BAR0 = sbase, BAR1 = sbase + 8;
    const u32 TILES = sbase + 1024;                // stage s: A +s*32768, B +16384

    const int tid = threadIdx.x;
    const int lane = tid & 31;
    const int wid = tid >> 5;
    const int wm = wid >> 1;                       // 0..1 (64-row warp tile)
    const int wn = wid & 1;                        // 0..1 (64-col warp tile)

    const int bid = blockIdx.x;
    const int g = bid / (GRPM * NB), r = bid % (GRPM * NB);
    const int bm = g * GRPM + (r % GRPM), bn = r / GRPM;
    const int mBase = bm * BM, nBase = bn * BN;

    float acc[4][8][4];
    #pragma unroll
    for (int m = 0; m < 4; m++)
        #pragma unroll
        for (int n = 0; n < 8; n++)
            #pragma unroll
            for (int q = 0; q < 4; q++) acc[m][n][q] = 0.f;

    if (tid == 0) { MBAR_INIT(BAR0, 1); MBAR_INIT(BAR1, 1); }
    __syncthreads();

    auto prefetch = [&](int kt) {
        if (tid == 0) {
            const int stage = kt & 1;
            const u32 bar = stage ? BAR1 : BAR0;
            const u32 dstA = TILES + stage * STAGEB;
            MBAR_EXPECT_TX(bar, 2 * TILE_BYTES);
            bulk_cp(dstA, XT + ((size_t)bm * 64 + kt) * TILE_BYTES, TILE_BYTES, bar);
            bulk_cp(dstA + TILE_BYTES, WT + ((size_t)bn * 64 + kt) * TILE_BYTES,
                    TILE_BYTES, bar);
        }
    };

    prefetch(0);

    for (int kt = 0; kt < STEPS; kt++) {
        const int stage = kt & 1;
        MBAR_WAIT(stage ? BAR1 : BAR0, (kt >> 1) & 1);   // data for kt resident
        __syncthreads();    // all warps done computing kt-1 (other stage reusable)
        if (kt + 1 < STEPS) prefetch(kt + 1);            // overlaps compute of kt

        const u32 Ab = TILES + stage * STAGEB;
        const u32 Bb = Ab + TILE_BYTES;
        #pragma unroll
        for (int kk = 0; kk < BK / 16; kk++) {
            u32 af[4][4];
            #pragma unroll
            for (int m = 0; m < 4; m++) {
                int row = wm * 64 + m * 16 + (lane & 15);
                u32 addr = Ab + sw128(row * 128 + (kk * 2 + (lane >> 4)) * 16);
                asm volatile(
                    "ldmatrix.sync.aligned.m8n8.x4.shared.b16 {%0,%1,%2,%3}, [%4];\n"
                    : "=r"(af[m][0]), "=r"(af[m][1]), "=r"(af[m][2]), "=r"(af[m][3])
                    : "r"(addr));
            }
            u32 bf[8][2];
            #pragma unroll
            for (int np = 0; np < 4; np++) {
                int grp = lane >> 3;
                int row = wn * 64 + np * 16 + (grp >> 1) * 8 + (lane & 7);
                u32 addr = Bb + sw128(row * 128 + (kk * 2 + (grp & 1)) * 16);
                u32 q0, q1, q2, q3;
                asm volatile(
                    "ldmatrix.sync.aligned.m8n8.x4.shared.b16 {%0,%1,%2,%3}, [%4];\n"
                    : "=r"(q0), "=r"(q1), "=r"(q2), "=r"(q3)
                    : "r"(addr));
                bf[np * 2][0] = q0;     bf[np * 2][1] = q1;
                bf[np * 2 + 1][0] = q2; bf[np * 2 + 1][1] = q3;
            }
            #pragma unroll
            for (int m = 0; m < 4; m++)
                #pragma unroll
                for (int n = 0; n < 8; n++)
                    asm volatile(
                        "mma.sync.aligned.m16n8k16.row.col.f32.f16.f16.f32 "
                        "{%0,%1,%2,%3}, {%4,%5,%6,%7}, {%8,%9}, {%0,%1,%2,%3};\n"
                        : "+f"(acc[m][n][0]), "+f"(acc[m][n][1]),
                          "+f"(acc[m][n][2]), "+f"(acc[m][n][3])
                        : "r"(af[m][0]), "r"(af[m][1]), "r"(af[m][2]), "r"(af[m][3]),
                          "r"(bf[n][0]), "r"(bf[n][1]));
        }
    }

    // epilogue: emulate fp16(dot)+fp16(bias) rounding, emit fp32
    #pragma unroll
    for (int n = 0; n < 8; n++) {
        int colBase = nBase + wn * 64 + n * 8 + 2 * (lane & 3);
        float b0 = __half2float(__float2half_rn(BIAS[colBase]));
        float b1 = __half2float(__float2half_rn(BIAS[colBase + 1]));
        #pragma unroll
        for (int m = 0; m < 4; m++) {
            int row0 = mBase + wm * 64 + m * 16 + (lane >> 2);
            float o00 = __half2float(__float2half_rn(
                          __half2float(__float2half_rn(acc[m][n][0])) + b0));
            float o01 = __half2float(__float2half_rn(
                          __half2float(__float2half_rn(acc[m][n][1])) + b1));
            float o10 = __half2float(__float2half_rn(
                          __half2float(__float2half_rn(acc[m][n][2])) + b0));
            float o11 = __half2float(__float2half_rn(
                          __half2float(__float2half_rn(acc[m][n][3])) + b1));
            *(float2*)(OUT + (size_t)row0 * NOUT + colBase) = make_float2(o00, o01);
            *(float2*)(OUT + (size_t)(row0 + 8) * NOUT + colBase) = make_float2(o10, o11);
        }
    }
}

extern "C" void kernel_launch(void* const* d_in, const int* in_sizes, int n_in,
                              void* d_out, int out_size)
{
    const float* x    = nullptr;
    const int*   wp   = nullptr;
    const float* amax = nullptr;
    const float* bias = nullptr;
    for (int i = 0; i < n_in; i++) {
        switch (in_sizes[i]) {
            case 16777216: x    = (const float*)d_in[i]; break;
            case 22544384: wp   = (const int*)d_in[i];   break;
            case 704512:   amax = (const float*)d_in[i]; break;
            case 11008:    bias = (const float*)d_in[i]; break;
            default: break;
        }
    }
    float* out = (float*)d_out;

    convert_x_kernel<<<8192, 256>>>(x);           // 2M chunks
    dequant_w_kernel<<<22016, 256>>>(wp, amax);   // 5.63M chunks

    cudaFuncSetAttribute(nf4_mma_gemm,
                         cudaFuncAttributeMaxDynamicSharedMemorySize, SMEM_BYTES);
    nf4_mma_gemm<<<(4096 / BM) * (11008 / BN), THREADS, SMEM_BYTES>>>(bias, out);
}